// round 11
// baseline (speedup 1.0000x reference)
#include <cuda_runtime.h>
#include <cuda_fp16.h>
#include <cstdint>

// ---------------------------------------------------------------- constants
#define B_     8
#define L_     64
#define NWIN_  256

// strides (bytes); all conflict-free for 8-row x 16B ldmatrix tiles (mod 128)
#define XN_STRIDE  144   // 64 fp16 used (128B) + pad
#define A_STRIDE   144   // global A row stride (72 fp16)
#define WP_STRIDE  80    // 32 fp16 used (64B) + pad
#define T_STRIDE   528   // 256 fp16 used (512B) + pad

// smem layout (bytes)
#define T_HI    0        // 64*528 = 33792
#define T_LO    33792
#define XN_OFF  67584    // 256*144 = 36864 (dead after GEMM1)
#define BUF0    67584    // Wp chunk buf0: 256*80 = 20480
#define BUF1    88064    // buf1 -> ends 108544
#define SMALL   108544   // mu @+0 (256B), rs @+256 (256B)
#define SMEM_TOTAL 109056

// ---------------------------------------------------------------- device scratch
__device__ __half g_A_hi[NWIN_ * 64 * 72];   // [w][row][72]
__device__ __half g_A_lo[NWIN_ * 64 * 72];
__device__ __half g_Wp[8 * 256 * 40];        // [chunk k=32][n][40]
__device__ float  g_Asum[NWIN_ * 64];

// ---------------------------------------------------------------- helpers
__device__ __forceinline__ uint32_t smem_u32(const void* p) {
    uint32_t a;
    asm("{ .reg .u64 t; cvta.to.shared.u64 t, %1; cvt.u32.u64 %0, t; }" : "=r"(a) : "l"(p));
    return a;
}
__device__ __forceinline__ void cp16(uint32_t saddr, const void* g) {
    asm volatile("cp.async.cg.shared.global [%0], [%1], 16;" :: "r"(saddr), "l"(g) : "memory");
}
#define CP_COMMIT() asm volatile("cp.async.commit_group;" ::: "memory")
#define CP_WAIT0()  asm volatile("cp.async.wait_group 0;" ::: "memory")
#define CP_WAIT1()  asm volatile("cp.async.wait_group 1;" ::: "memory")

__device__ __forceinline__ void mma16816(float* d, const uint32_t* a, uint32_t b0, uint32_t b1) {
    asm volatile(
        "mma.sync.aligned.m16n8k16.row.col.f32.f16.f16.f32 "
        "{%0,%1,%2,%3}, {%4,%5,%6,%7}, {%8,%9}, {%0,%1,%2,%3};"
        : "+f"(d[0]), "+f"(d[1]), "+f"(d[2]), "+f"(d[3])
        : "r"(a[0]), "r"(a[1]), "r"(a[2]), "r"(a[3]), "r"(b0), "r"(b1));
}
__device__ __forceinline__ void ldm_x4(uint32_t* r, uint32_t saddr) {
    asm volatile("ldmatrix.sync.aligned.m8n8.x4.shared.b16 {%0,%1,%2,%3}, [%4];"
        : "=r"(r[0]), "=r"(r[1]), "=r"(r[2]), "=r"(r[3]) : "r"(saddr));
}
__device__ __forceinline__ uint32_t pack2h(float v0, float v1) {
    __half2 t; t.x = __float2half_rn(v0); t.y = __float2half_rn(v1);
    return *reinterpret_cast<uint32_t*>(&t);
}
__device__ __forceinline__ uint32_t pack2l(float v0, float v1) {
    __half h0 = __float2half_rn(v0), h1 = __float2half_rn(v1);
    __half2 t;
    t.x = __float2half_rn(v0 - __half2float(h0));
    t.y = __float2half_rn(v1 - __half2float(h1));
    return *reinterpret_cast<uint32_t*>(&t);
}
// global token row for window w (0..255), token q (0..63), batch b
__device__ __forceinline__ int grow1(int b, int w, int q) {
    return ((b * 256 + (w >> 2) * 4 + (q >> 4)) * 64 + (w & 3) * 16 + (q & 15));
}

// ---------------------------------------------------------------- prologue:
// bid < 512 : pack_A part (32 rows of A_w = deg_w @ edge_w), ILP-8 inner loop
// bid >= 512: pack_Wp row n = bid-512
__global__ void __launch_bounds__(256)
prologue_kernel(const float* __restrict__ edge, const float* __restrict__ deg,
                const float* __restrict__ Wp) {
    __shared__ float eg[64 * 64];     // 16 KB
    __shared__ float dgp[32 * 64];    // 8 KB
    const int tid = threadIdx.x;
    if (blockIdx.x >= 512) {
        const int n = blockIdx.x - 512, k = tid;
        const float v = Wp[n * 256 + k];
        g_Wp[(k >> 5) * (256 * 40) + n * 40 + (k & 31)] = __float2half_rn(v);
        return;
    }
    const int w = blockIdx.x >> 1, part = blockIdx.x & 1;
    {
        const float4* eG = (const float4*)(edge + (size_t)w * 4096);
        float4* eS = (float4*)eg;
        for (int i = tid; i < 1024; i += 256) eS[i] = eG[i];
        const float4* dG = (const float4*)(deg + (size_t)w * 4096 + part * 2048);
        float4* dS = (float4*)dgp;
        for (int i = tid; i < 512; i += 256) dS[i] = dG[i];
    }
    __syncthreads();
    const int row = tid >> 3;             // 0..31
    const int q0  = (tid & 7) * 8;        // 0..56
    float acc[8];
#pragma unroll
    for (int j = 0; j < 8; j++) acc[j] = 0.f;
#pragma unroll 4
    for (int k = 0; k < 64; k++) {
        const float a = dgp[row * 64 + k];
        const float4 e0 = *(const float4*)&eg[k * 64 + q0];
        const float4 e1 = *(const float4*)&eg[k * 64 + q0 + 4];
        acc[0] = fmaf(a, e0.x, acc[0]); acc[1] = fmaf(a, e0.y, acc[1]);
        acc[2] = fmaf(a, e0.z, acc[2]); acc[3] = fmaf(a, e0.w, acc[3]);
        acc[4] = fmaf(a, e1.x, acc[4]); acc[5] = fmaf(a, e1.y, acc[5]);
        acc[6] = fmaf(a, e1.z, acc[6]); acc[7] = fmaf(a, e1.w, acc[7]);
    }
    const int p = part * 32 + row;
    __half* bh = g_A_hi + (size_t)w * 64 * 72 + p * 72 + q0;
    __half* bl = g_A_lo + (size_t)w * 64 * 72 + p * 72 + q0;
    float rsum = 0.f;
#pragma unroll
    for (int j = 0; j < 8; j++) {
        rsum += acc[j];
        __half h = __float2half_rn(acc[j]);
        bh[j] = h;
        bl[j] = __float2half_rn(acc[j] - __half2float(h));
    }
    rsum += __shfl_xor_sync(0xFFFFFFFFu, rsum, 1);
    rsum += __shfl_xor_sync(0xFFFFFFFFu, rsum, 2);
    rsum += __shfl_xor_sync(0xFFFFFFFFu, rsum, 4);
    if ((tid & 7) == 0) g_Asum[w * 64 + p] = rsum;
}

// ---------------------------------------------------------------- main kernel
__global__ void __launch_bounds__(256, 2)
window_kernel(const float* __restrict__ x,
              const float* __restrict__ gamma,
              const float* __restrict__ beta,
              const float* __restrict__ bp,
              float* __restrict__ out) {
    extern __shared__ char sm[];
    const int tid  = threadIdx.x;
    const int warp = tid >> 5;
    const int lane = tid & 31;
    const int w    = blockIdx.x;
    const int b    = blockIdx.y;

    float* mu_s = (float*)(sm + SMALL);
    float* rs_s = (float*)(sm + SMALL + 256);

    // ---- LayerNorm stats: warp per token ----------------------------------
    for (int r = 0; r < 8; r++) {
        const int t = warp * 8 + r;
        const float* xr = x + (size_t)grow1(b, w, t) * 256;
        const float4 v0 = *(const float4*)(xr + lane * 4);
        const float4 v1 = *(const float4*)(xr + 128 + lane * 4);
        float s  = v0.x + v0.y + v0.z + v0.w + v1.x + v1.y + v1.z + v1.w;
        float s2 = v0.x*v0.x + v0.y*v0.y + v0.z*v0.z + v0.w*v0.w
                 + v1.x*v1.x + v1.y*v1.y + v1.z*v1.z + v1.w*v1.w;
#pragma unroll
        for (int o = 16; o > 0; o >>= 1) {
            s  += __shfl_xor_sync(0xFFFFFFFFu, s,  o);
            s2 += __shfl_xor_sync(0xFFFFFFFFu, s2, o);
        }
        if (lane == 0) {
            const float mean = s * (1.f / 256.f);
            mu_s[t] = mean;
            rs_s[t] = rsqrtf(s2 * (1.f / 256.f) - mean * mean + 1e-5f);
        }
    }
    __syncthreads();

    // ---- normalize + write xn_T[c][q] single fp16 plane -------------------
    {
        const int c = tid;
        const float gc = gamma[c], bc = beta[c];
        char* ph = sm + XN_OFF + c * XN_STRIDE;
#pragma unroll 4
        for (int qp = 0; qp < 32; qp++) {
            const int q0 = 2 * qp;
            const float x0 = x[(size_t)grow1(b, w, q0) * 256 + c];
            const float x1 = x[(size_t)grow1(b, w, q0 + 1) * 256 + c];
            const float v0 = (x0 - mu_s[q0]) * rs_s[q0] * gc + bc;
            const float v1 = (x1 - mu_s[q0 + 1]) * rs_s[q0 + 1] * gc + bc;
            *(uint32_t*)(ph + qp * 4) = pack2h(v0, v1);
        }
    }
    __syncthreads();

    // warp tile: 32 (m) x 64 (n)
    const int wm = (warp & 1) * 32;
    const int wn = (warp >> 1) * 64;
    const int r4 = lane >> 2;          // 0..7
    const int j4 = (lane & 3) * 4;     // byte offset of k-pair
    const uint32_t smb = smem_u32(sm);
    // ldmatrix lane addressing
    const int lmA = lane & 15;                               // A row within 16
    const int lkA = (lane >> 4) * 16;                        // A k-byte offset
    const int lnB = (lane & 7) + ((lane >> 4) & 1) * 8;      // B n-row within 16
    const int lkB = ((lane >> 3) & 1) * 16;                  // B k-byte offset

    float D[2][8][4];
#pragma unroll
    for (int mb = 0; mb < 2; mb++)
#pragma unroll
        for (int nb = 0; nb < 8; nb++)
#pragma unroll
            for (int v = 0; v < 4; v++) D[mb][nb][v] = 0.f;

    // ---- GEMM1: t = A_w @ xn  (K=64, A hi/lo from L2, xn via ldmatrix) ----
    {
        const char* gAh = (const char*)(g_A_hi + (size_t)w * 64 * 72);
        const char* gAl = (const char*)(g_A_lo + (size_t)w * 64 * 72);
#pragma unroll
        for (int ks = 0; ks < 4; ks++) {
            uint32_t Ah[2][4], Al[2][4];
#pragma unroll
            for (int mb = 0; mb < 2; mb++) {
                const int aoff = (wm + mb * 16 + r4) * A_STRIDE + ks * 32 + j4;
                Ah[mb][0] = *(const uint32_t*)(gAh + aoff);
                Ah[mb][1] = *(const uint32_t*)(gAh + aoff + 8 * A_STRIDE);
                Ah[mb][2] = *(const uint32_t*)(gAh + aoff + 16);
                Ah[mb][3] = *(const uint32_t*)(gAh + aoff + 8 * A_STRIDE + 16);
                Al[mb][0] = *(const uint32_t*)(gAl + aoff);
                Al[mb][1] = *(const uint32_t*)(gAl + aoff + 8 * A_STRIDE);
                Al[mb][2] = *(const uint32_t*)(gAl + aoff + 16);
                Al[mb][3] = *(const uint32_t*)(gAl + aoff + 8 * A_STRIDE + 16);
            }
            uint32_t Bv[4][4];
#pragma unroll
            for (int P = 0; P < 4; P++)
                ldm_x4(Bv[P], smb + XN_OFF + (wn + P * 16 + lnB) * XN_STRIDE + ks * 32 + lkB);
#pragma unroll
            for (int nb = 0; nb < 8; nb++) {
                const uint32_t b0 = Bv[nb >> 1][(nb & 1) * 2];
                const uint32_t b1 = Bv[nb >> 1][(nb & 1) * 2 + 1];
#pragma unroll
                for (int mb = 0; mb < 2; mb++) {
                    mma16816(D[mb][nb], Ah[mb], b0, b1);
                    mma16816(D[mb][nb], Al[mb], b0, b1);
                }
            }
        }
    }

    // ---- store t as fp16 hi/lo, row-major [m][k] --------------------------
#pragma unroll
    for (int mb = 0; mb < 2; mb++) {
#pragma unroll
        for (int nb = 0; nb < 8; nb++) {
            const int m0 = wm + mb * 16 + r4;
            const int n0 = wn + nb * 8 + (lane & 3) * 2;
            float* d = D[mb][nb];
            *(uint32_t*)(sm + T_HI + m0 * T_STRIDE + n0 * 2)       = pack2h(d[0], d[1]);
            *(uint32_t*)(sm + T_LO + m0 * T_STRIDE + n0 * 2)       = pack2l(d[0], d[1]);
            *(uint32_t*)(sm + T_HI + (m0 + 8) * T_STRIDE + n0 * 2) = pack2h(d[2], d[3]);
            *(uint32_t*)(sm + T_LO + (m0 + 8) * T_STRIDE + n0 * 2) = pack2l(d[2], d[3]);
        }
    }
    __syncthreads();   // t visible; xn region now dead -> Wp buffers

    // ---- prefetch Wp chunks 0,1 (20480 B each) ----------------------------
    {
        const uint32_t s0 = smb + BUF0;
        const uint32_t s1 = smb + BUF1;
        const char* g0 = (const char*)g_Wp;
        for (int i = tid; i < 1280; i += 256) cp16(s0 + i * 16, g0 + i * 16);
        CP_COMMIT();
        for (int i = tid; i < 1280; i += 256) cp16(s1 + i * 16, g0 + 20480 + i * 16);
        CP_COMMIT();
    }

    // zero accumulators for GEMM2
#pragma unroll
    for (int mb = 0; mb < 2; mb++)
#pragma unroll
        for (int nb = 0; nb < 8; nb++)
#pragma unroll
            for (int v = 0; v < 4; v++) D[mb][nb][v] = 0.f;

    // ---- GEMM2: out = t @ Wp^T  (K=256, 8 chunks of 32, double-buffered) --
    for (int ch = 0; ch < 8; ch++) {
        if (ch < 7) { CP_WAIT1(); } else { CP_WAIT0(); }
        __syncthreads();
        const int bufo = (ch & 1) ? BUF1 : BUF0;
#pragma unroll
        for (int ks = 0; ks < 2; ks++) {
            uint32_t Ah[2][4], Al[2][4];
#pragma unroll
            for (int mb = 0; mb < 2; mb++) {
                const uint32_t abase = smb + (wm + mb * 16 + lmA) * T_STRIDE + ch * 64 + ks * 32 + lkA;
                ldm_x4(Ah[mb], abase + T_HI);
                ldm_x4(Al[mb], abase + T_LO);
            }
            uint32_t Bv[4][4];
#pragma unroll
            for (int P = 0; P < 4; P++)
                ldm_x4(Bv[P], smb + bufo + (wn + P * 16 + lnB) * WP_STRIDE + ks * 32 + lkB);
#pragma unroll
            for (int nb = 0; nb < 8; nb++) {
                const uint32_t b0 = Bv[nb >> 1][(nb & 1) * 2];
                const uint32_t b1 = Bv[nb >> 1][(nb & 1) * 2 + 1];
#pragma unroll
                for (int mb = 0; mb < 2; mb++) {
                    mma16816(D[mb][nb], Ah[mb], b0, b1);
                    mma16816(D[mb][nb], Al[mb], b0, b1);
                }
            }
        }
        __syncthreads();   // all warps done with this buffer
        if (ch < 6) {      // refill with chunk ch+2
            const uint32_t sb = smb + bufo;
            const char* g = (const char*)g_Wp + (ch + 2) * 20480;
            for (int i = tid; i < 1280; i += 256) cp16(sb + i * 16, g + i * 16);
            CP_COMMIT();
        }
    }

    // ---- epilogue: out = D + rowsum(A)[m]*bp[n], window-reverse -----------
#pragma unroll
    for (int mb = 0; mb < 2; mb++) {
        const int m0 = wm + mb * 16 + r4;
        const int rowA = grow1(b, w, m0);
        const int rowB = grow1(b, w, m0 + 8);
        const float sA = g_Asum[w * 64 + m0];
        const float sB = g_Asum[w * 64 + m0 + 8];
#pragma unroll
        for (int nb = 0; nb < 8; nb++) {
            const int n0 = wn + nb * 8 + (lane & 3) * 2;
            const float2 bpv = *(const float2*)(bp + n0);
            float* d = D[mb][nb];
            float2 z0, z1;
            z0.x = d[0] + sA * bpv.x;  z0.y = d[1] + sA * bpv.y;
            z1.x = d[2] + sB * bpv.x;  z1.y = d[3] + sB * bpv.y;
            *(float2*)(out + (size_t)rowA * 256 + n0) = z0;
            *(float2*)(out + (size_t)rowB * 256 + n0) = z1;
        }
    }
}

// ---------------------------------------------------------------- launch
extern "C" void kernel_launch(void* const* d_in, const int* in_sizes, int n_in,
                              void* d_out, int out_size) {
    (void)in_sizes; (void)n_in; (void)out_size;
    const float* x     = (const float*)d_in[0];
    const float* gamma = (const float*)d_in[1];
    const float* beta  = (const float*)d_in[2];
    const float* Wp    = (const float*)d_in[3];
    const float* bp    = (const float*)d_in[4];
    const float* edge  = (const float*)d_in[5];
    const float* deg   = (const float*)d_in[6];
    float* out = (float*)d_out;

    prologue_kernel<<<512 + 256, 256>>>(edge, deg, Wp);

    cudaFuncSetAttribute(window_kernel, cudaFuncAttributeMaxDynamicSharedMemorySize, SMEM_TOTAL);
    window_kernel<<<dim3(NWIN_, B_), 256, SMEM_TOTAL>>>(x, gamma, beta, bp, out);
}

// round 12
// speedup vs baseline: 1.1440x; 1.1440x over previous
#include <cuda_runtime.h>
#include <cuda_fp16.h>
#include <cstdint>

// ---------------------------------------------------------------- constants
#define B_     8
#define L_     64
#define NWIN_  256

// strides (bytes)
#define A_STRIDE   144   // global A row stride (72 fp16)
#define WP_STRIDE  80    // 32 fp16 used (64B) + pad
#define T_STRIDE   528   // 256 fp16 used (512B) + pad ; also xn_rm stride (64 fp16 rows... row=token, 256 ch)

// smem layout (bytes)
// Region 0..67584: first used as xn_rm (64 rows x 528, only 512B used per row),
// then (after GEMM1 barrier) as t_hi (0..33792) + t_lo (33792..67584).
#define XN_RM   0
#define T_HI    0
#define T_LO    33792
#define BUF0    67584    // Wp chunk buf0: 256*80 = 20480
#define BUF1    88064    // buf1 -> ends 108544
#define SMEM_TOTAL 108544

// ---------------------------------------------------------------- device scratch
__device__ __half g_A_hi[NWIN_ * 64 * 72];   // [w][row][72]
__device__ __half g_A_lo[NWIN_ * 64 * 72];
__device__ __half g_Wp[8 * 256 * 40];        // [chunk k=32][n][40]
__device__ float  g_Asum[NWIN_ * 64];

// ---------------------------------------------------------------- helpers
__device__ __forceinline__ uint32_t smem_u32(const void* p) {
    uint32_t a;
    asm("{ .reg .u64 t; cvta.to.shared.u64 t, %1; cvt.u32.u64 %0, t; }" : "=r"(a) : "l"(p));
    return a;
}
__device__ __forceinline__ void cp16(uint32_t saddr, const void* g) {
    asm volatile("cp.async.cg.shared.global [%0], [%1], 16;" :: "r"(saddr), "l"(g) : "memory");
}
#define CP_COMMIT() asm volatile("cp.async.commit_group;" ::: "memory")
#define CP_WAIT0()  asm volatile("cp.async.wait_group 0;" ::: "memory")
#define CP_WAIT1()  asm volatile("cp.async.wait_group 1;" ::: "memory")

__device__ __forceinline__ void mma16816(float* d, const uint32_t* a, uint32_t b0, uint32_t b1) {
    asm volatile(
        "mma.sync.aligned.m16n8k16.row.col.f32.f16.f16.f32 "
        "{%0,%1,%2,%3}, {%4,%5,%6,%7}, {%8,%9}, {%0,%1,%2,%3};"
        : "+f"(d[0]), "+f"(d[1]), "+f"(d[2]), "+f"(d[3])
        : "r"(a[0]), "r"(a[1]), "r"(a[2]), "r"(a[3]), "r"(b0), "r"(b1));
}
__device__ __forceinline__ void ldm_x4(uint32_t* r, uint32_t saddr) {
    asm volatile("ldmatrix.sync.aligned.m8n8.x4.shared.b16 {%0,%1,%2,%3}, [%4];"
        : "=r"(r[0]), "=r"(r[1]), "=r"(r[2]), "=r"(r[3]) : "r"(saddr));
}
__device__ __forceinline__ void ldm_x4_t(uint32_t* r, uint32_t saddr) {
    asm volatile("ldmatrix.sync.aligned.m8n8.x4.trans.shared.b16 {%0,%1,%2,%3}, [%4];"
        : "=r"(r[0]), "=r"(r[1]), "=r"(r[2]), "=r"(r[3]) : "r"(saddr));
}
__device__ __forceinline__ uint32_t pack2h(float v0, float v1) {
    __half2 t; t.x = __float2half_rn(v0); t.y = __float2half_rn(v1);
    return *reinterpret_cast<uint32_t*>(&t);
}
__device__ __forceinline__ uint32_t pack2l(float v0, float v1) {
    __half h0 = __float2half_rn(v0), h1 = __float2half_rn(v1);
    __half2 t;
    t.x = __float2half_rn(v0 - __half2float(h0));
    t.y = __float2half_rn(v1 - __half2float(h1));
    return *reinterpret_cast<uint32_t*>(&t);
}
// global token row for window w (0..255), token q (0..63), batch b
__device__ __forceinline__ int grow1(int b, int w, int q) {
    return ((b * 256 + (w >> 2) * 4 + (q >> 4)) * 64 + (w & 3) * 16 + (q & 15));
}

// ---------------------------------------------------------------- prologue 1 (R10 version):
// A_w = deg_w @ edge_w -> fp16 hi/lo padded rows + rowsums. 4 CTAs/window.
__global__ void __launch_bounds__(256)
pack_A_kernel(const float* __restrict__ edge, const float* __restrict__ deg) {
    __shared__ float eg[64 * 64];
    __shared__ float dgp[16 * 64];
    const int w = blockIdx.x >> 2, part = blockIdx.x & 3;
    const int tid = threadIdx.x;
    {
        const float4* eG = (const float4*)(edge + (size_t)w * 4096);
        float4* eS = (float4*)eg;
        for (int i = tid; i < 1024; i += 256) eS[i] = eG[i];
        const float4* dG = (const float4*)(deg + (size_t)w * 4096 + part * 1024);
        float4* dS = (float4*)dgp;
        if (tid < 256) dS[tid] = dG[tid];
    }
    __syncthreads();
    const int row = tid >> 4;             // 0..15
    const int q0  = (tid & 15) * 4;       // 0..60
    float a0 = 0.f, a1 = 0.f, a2 = 0.f, a3 = 0.f;
#pragma unroll 8
    for (int k = 0; k < 64; k++) {
        const float a = dgp[row * 64 + k];
        const float4 e = *(const float4*)&eg[k * 64 + q0];
        a0 = fmaf(a, e.x, a0); a1 = fmaf(a, e.y, a1);
        a2 = fmaf(a, e.z, a2); a3 = fmaf(a, e.w, a3);
    }
    const int p = part * 16 + row;
    __half* bh = g_A_hi + (size_t)w * 64 * 72 + p * 72 + q0;
    __half* bl = g_A_lo + (size_t)w * 64 * 72 + p * 72 + q0;
    const float v[4] = {a0, a1, a2, a3};
#pragma unroll
    for (int j = 0; j < 4; j++) {
        __half h = __float2half_rn(v[j]);
        bh[j] = h;
        bl[j] = __float2half_rn(v[j] - __half2float(h));
    }
    float rsum = a0 + a1 + a2 + a3;
#pragma unroll
    for (int o = 1; o < 16; o <<= 1) rsum += __shfl_xor_sync(0xFFFFFFFFu, rsum, o);
    if ((tid & 15) == 0) g_Asum[w * 64 + p] = rsum;
}

// ---------------------------------------------------------------- prologue 2:
__global__ void __launch_bounds__(256)
pack_Wp_kernel(const float* __restrict__ Wp) {
    const int n = blockIdx.x, k = threadIdx.x;
    const float v = Wp[n * 256 + k];
    g_Wp[(k >> 5) * (256 * 40) + n * 40 + (k & 31)] = __float2half_rn(v);
}

// ---------------------------------------------------------------- main kernel
__global__ void __launch_bounds__(256, 2)
window_kernel(const float* __restrict__ x,
              const float* __restrict__ gamma,
              const float* __restrict__ beta,
              const float* __restrict__ bp,
              float* __restrict__ out) {
    extern __shared__ char sm[];
    const int tid  = threadIdx.x;
    const int warp = tid >> 5;
    const int lane = tid & 31;
    const int w    = blockIdx.x;
    const int b    = blockIdx.y;
    const uint32_t smb = smem_u32(sm);

    // ---- prefetch Wp chunks 0,1 under the LN pass + GEMM1 -----------------
    {
        const char* g0 = (const char*)g_Wp;
        for (int i = tid; i < 1280; i += 256) cp16(smb + BUF0 + i * 16, g0 + i * 16);
        CP_COMMIT();
        for (int i = tid; i < 1280; i += 256) cp16(smb + BUF1 + i * 16, g0 + 20480 + i * 16);
        CP_COMMIT();
    }

    // ---- single-pass LayerNorm: stats + normalize in regs, write xn row-major
    {
        const float4 gm0 = *(const float4*)(gamma + lane * 4);
        const float4 gm1 = *(const float4*)(gamma + 128 + lane * 4);
        const float4 bt0 = *(const float4*)(beta + lane * 4);
        const float4 bt1 = *(const float4*)(beta + 128 + lane * 4);
        for (int r = 0; r < 8; r++) {
            const int t = warp * 8 + r;
            const float* xr = x + (size_t)grow1(b, w, t) * 256;
            const float4 v0 = *(const float4*)(xr + lane * 4);
            const float4 v1 = *(const float4*)(xr + 128 + lane * 4);
            float s  = v0.x + v0.y + v0.z + v0.w + v1.x + v1.y + v1.z + v1.w;
            float s2 = v0.x*v0.x + v0.y*v0.y + v0.z*v0.z + v0.w*v0.w
                     + v1.x*v1.x + v1.y*v1.y + v1.z*v1.z + v1.w*v1.w;
#pragma unroll
            for (int o = 16; o > 0; o >>= 1) {
                s  += __shfl_xor_sync(0xFFFFFFFFu, s,  o);
                s2 += __shfl_xor_sync(0xFFFFFFFFu, s2, o);
            }
            const float mean = s * (1.f / 256.f);
            const float rstd = rsqrtf(s2 * (1.f / 256.f) - mean * mean + 1e-5f);
            uint2 u0, u1;
            u0.x = pack2h((v0.x - mean) * rstd * gm0.x + bt0.x,
                          (v0.y - mean) * rstd * gm0.y + bt0.y);
            u0.y = pack2h((v0.z - mean) * rstd * gm0.z + bt0.z,
                          (v0.w - mean) * rstd * gm0.w + bt0.w);
            u1.x = pack2h((v1.x - mean) * rstd * gm1.x + bt1.x,
                          (v1.y - mean) * rstd * gm1.y + bt1.y);
            u1.y = pack2h((v1.z - mean) * rstd * gm1.z + bt1.z,
                          (v1.w - mean) * rstd * gm1.w + bt1.w);
            *(uint2*)(sm + XN_RM + t * T_STRIDE + lane * 8)       = u0;
            *(uint2*)(sm + XN_RM + t * T_STRIDE + 256 + lane * 8) = u1;
        }
    }
    __syncthreads();

    // warp tile: 32 (m) x 64 (n)
    const int wm = (warp & 1) * 32;
    const int wn = (warp >> 1) * 64;
    const int r4 = lane >> 2;          // 0..7
    const int j4 = (lane & 3) * 4;     // byte offset of k-pair
    // ldmatrix lane addressing
    const int lmA = lane & 15;                               // A row within 16 (non-trans)
    const int lkA = (lane >> 4) * 16;                        // A k-byte offset
    const int ktB = (lane & 7) + ((lane >> 3) & 1) * 8;      // trans-B k row
    const int nOB = (lane >> 4) * 8;                         // trans-B n offset

    float D[2][8][4];
#pragma unroll
    for (int mb = 0; mb < 2; mb++)
#pragma unroll
        for (int nb = 0; nb < 8; nb++)
#pragma unroll
            for (int v = 0; v < 4; v++) D[mb][nb][v] = 0.f;

    // ---- GEMM1: t = A_w @ xn  (K=64; A hi/lo from L2, xn via ldmatrix.trans)
    {
        const char* gAh = (const char*)(g_A_hi + (size_t)w * 64 * 72);
        const char* gAl = (const char*)(g_A_lo + (size_t)w * 64 * 72);
#pragma unroll
        for (int ks = 0; ks < 4; ks++) {
            uint32_t Ah[2][4], Al[2][4];
#pragma unroll
            for (int mb = 0; mb < 2; mb++) {
                const int aoff = (wm + mb * 16 + r4) * A_STRIDE + ks * 32 + j4;
                Ah[mb][0] = *(const uint32_t*)(gAh + aoff);
                Ah[mb][1] = *(const uint32_t*)(gAh + aoff + 8 * A_STRIDE);
                Ah[mb][2] = *(const uint32_t*)(gAh + aoff + 16);
                Ah[mb][3] = *(const uint32_t*)(gAh + aoff + 8 * A_STRIDE + 16);
                Al[mb][0] = *(const uint32_t*)(gAl + aoff);
                Al[mb][1] = *(const uint32_t*)(gAl + aoff + 8 * A_STRIDE);
                Al[mb][2] = *(const uint32_t*)(gAl + aoff + 16);
                Al[mb][3] = *(const uint32_t*)(gAl + aoff + 8 * A_STRIDE + 16);
            }
            uint32_t Bv[4][4];
#pragma unroll
            for (int P = 0; P < 4; P++)
                ldm_x4_t(Bv[P], smb + XN_RM + (ks * 16 + ktB) * T_STRIDE + (wn + P * 16 + nOB) * 2);
#pragma unroll
            for (int nb = 0; nb < 8; nb++) {
                const uint32_t b0 = Bv[nb >> 1][(nb & 1) * 2];
                const uint32_t b1 = Bv[nb >> 1][(nb & 1) * 2 + 1];
#pragma unroll
                for (int mb = 0; mb < 2; mb++) {
                    mma16816(D[mb][nb], Ah[mb], b0, b1);
                    mma16816(D[mb][nb], Al[mb], b0, b1);
                }
            }
        }
    }
    __syncthreads();   // all xn reads done; region becomes t_hi/t_lo

    // ---- store t as fp16 hi/lo, row-major [m][k] --------------------------
#pragma unroll
    for (int mb = 0; mb < 2; mb++) {
#pragma unroll
        for (int nb = 0; nb < 8; nb++) {
            const int m0 = wm + mb * 16 + r4;
            const int n0 = wn + nb * 8 + (lane & 3) * 2;
            float* d = D[mb][nb];
            *(uint32_t*)(sm + T_HI + m0 * T_STRIDE + n0 * 2)       = pack2h(d[0], d[1]);
            *(uint32_t*)(sm + T_LO + m0 * T_STRIDE + n0 * 2)       = pack2l(d[0], d[1]);
            *(uint32_t*)(sm + T_HI + (m0 + 8) * T_STRIDE + n0 * 2) = pack2h(d[2], d[3]);
            *(uint32_t*)(sm + T_LO + (m0 + 8) * T_STRIDE + n0 * 2) = pack2l(d[2], d[3]);
        }
    }

    // zero accumulators for GEMM2
#pragma unroll
    for (int mb = 0; mb < 2; mb++)
#pragma unroll
        for (int nb = 0; nb < 8; nb++)
#pragma unroll
            for (int v = 0; v < 4; v++) D[mb][nb][v] = 0.f;

    // ---- GEMM2: out = t @ Wp^T  (K=256, 8 chunks of 32, double-buffered) --
    for (int ch = 0; ch < 8; ch++) {
        if (ch < 7) { CP_WAIT1(); } else { CP_WAIT0(); }
        __syncthreads();   // orders t stores (ch=0) + buffer reuse + cp arrivals
        const int bufo = (ch & 1) ? BUF1 : BUF0;
#pragma unroll
        for (int ks = 0; ks < 2; ks++) {
            uint32_t Ah[2][4], Al[2][4];
#pragma unroll
            for (int mb = 0; mb < 2; mb++) {
                const uint32_t abase = smb + (wm + mb * 16 + lmA) * T_STRIDE + ch * 64 + ks * 32 + lkA;
                ldm_x4(Ah[mb], abase + T_HI);
                ldm_x4(Al[mb], abase + T_LO);
            }
            uint32_t Bv[4][4];
#pragma unroll
            for (int P = 0; P < 4; P++)
                ldm_x4(Bv[P], smb + bufo + (wn + P * 16 + (lane & 7) + ((lane >> 4) & 1) * 8) * WP_STRIDE
                              + ks * 32 + ((lane >> 3) & 1) * 16);
#pragma unroll
            for (int nb = 0; nb < 8; nb++) {
                const uint32_t b0 = Bv[nb >> 1][(nb & 1) * 2];
                const uint32_t b1 = Bv[nb >> 1][(nb & 1) * 2 + 1];
#pragma unroll
                for (int mb = 0; mb < 2; mb++) {
                    mma16816(D[mb][nb], Ah[mb], b0, b1);
                    mma16816(D[mb][nb], Al[mb], b0, b1);
                }
            }
        }
        __syncthreads();   // all warps done with this buffer
        if (ch < 6) {      // refill with chunk ch+2
            const uint32_t sb = smb + bufo;
            const char* g = (const char*)g_Wp + (ch + 2) * 20480;
            for (int i = tid; i < 1280; i += 256) cp16(sb + i * 16, g + i * 16);
            CP_COMMIT();
        }
    }

    // ---- epilogue: out = D + rowsum(A)[m]*bp[n], window-reverse -----------
#pragma unroll
    for (int mb = 0; mb < 2; mb++) {
        const int m0 = wm + mb * 16 + r4;
        const int rowA = grow1(b, w, m0);
        const int rowB = grow1(b, w, m0 + 8);
        const float sA = g_Asum[w * 64 + m0];
        const float sB = g_Asum[w * 64 + m0 + 8];
#pragma unroll
        for (int nb = 0; nb < 8; nb++) {
            const int n0 = wn + nb * 8 + (lane & 3) * 2;
            const float2 bpv = *(const float2*)(bp + n0);
            float* d = D[mb][nb];
            float2 z0, z1;
            z0.x = d[0] + sA * bpv.x;  z0.y = d[1] + sA * bpv.y;
            z1.x = d[2] + sB * bpv.x;  z1.y = d[3] + sB * bpv.y;
            *(float2*)(out + (size_t)rowA * 256 + n0) = z0;
            *(float2*)(out + (size_t)rowB * 256 + n0) = z1;
        }
    }
}

// ---------------------------------------------------------------- launch
extern "C" void kernel_launch(void* const* d_in, const int* in_sizes, int n_in,
                              void* d_out, int out_size) {
    (void)in_sizes; (void)n_in; (void)out_size;
    const float* x     = (const float*)d_in[0];
    const float* gamma = (const float*)d_in[1];
    const float* beta  = (const float*)d_in[2];
    const float* Wp    = (const float*)d_in[3];
    const float* bp    = (const float*)d_in[4];
    const float* edge  = (const float*)d_in[5];
    const float* deg   = (const float*)d_in[6];
    float* out = (float*)d_out;

    pack_A_kernel<<<NWIN_ * 4, 256>>>(edge, deg);
    pack_Wp_kernel<<<256, 256>>>(Wp);

    cudaFuncSetAttribute(window_kernel, cudaFuncAttributeMaxDynamicSharedMemorySize, SMEM_TOTAL);
    window_kernel<<<dim3(NWIN_, B_), 256, SMEM_TOTAL>>>(x, gamma, beta, bp, out);
}

// round 14
// speedup vs baseline: 1.2999x; 1.1363x over previous
#include <cuda_runtime.h>
#include <cuda_fp16.h>
#include <cstdint>

// ---------------------------------------------------------------- constants
#define B_     8
#define L_     64
#define NWIN_  256

// strides (bytes)
#define A_STRIDE   144   // global A row stride (72 fp16)
#define WP_STRIDE  80    // 32 fp16 used (64B) + pad
#define T_STRIDE   528   // 256 fp16 used (512B) + pad

// smem layout (bytes)
// Region 0..33792: first xn_rm (64 x 528; written row-major), then t_hi.
#define XN_RM   0
#define T_HI    0
#define BUF0    67584    // Wp chunk buf0: 256*80 = 20480
#define BUF1    88064    // buf1 -> ends 108544
#define SMEM_TOTAL 108544

// ---------------------------------------------------------------- device scratch
__device__ __half g_A_hi[NWIN_ * 64 * 72];   // [w][row][72]
__device__ __half g_A_lo[NWIN_ * 64 * 72];
__device__ __half g_Wp[8 * 256 * 40];        // [chunk k=32][n][40]
__device__ float  g_Asum[NWIN_ * 64];

// ---------------------------------------------------------------- helpers
__device__ __forceinline__ uint32_t smem_u32(const void* p) {
    uint32_t a;
    asm("{ .reg .u64 t; cvta.to.shared.u64 t, %1; cvt.u32.u64 %0, t; }" : "=r"(a) : "l"(p));
    return a;
}
__device__ __forceinline__ void cp16(uint32_t saddr, const void* g) {
    asm volatile("cp.async.cg.shared.global [%0], [%1], 16;" :: "r"(saddr), "l"(g) : "memory");
}
#define CP_COMMIT() asm volatile("cp.async.commit_group;" ::: "memory")
#define CP_WAIT0()  asm volatile("cp.async.wait_group 0;" ::: "memory")
#define CP_WAIT1()  asm volatile("cp.async.wait_group 1;" ::: "memory")

__device__ __forceinline__ void mma16816(float* d, const uint32_t* a, uint32_t b0, uint32_t b1) {
    asm volatile(
        "mma.sync.aligned.m16n8k16.row.col.f32.f16.f16.f32 "
        "{%0,%1,%2,%3}, {%4,%5,%6,%7}, {%8,%9}, {%0,%1,%2,%3};"
        : "+f"(d[0]), "+f"(d[1]), "+f"(d[2]), "+f"(d[3])
        : "r"(a[0]), "r"(a[1]), "r"(a[2]), "r"(a[3]), "r"(b0), "r"(b1));
}
__device__ __forceinline__ void ldm_x4(uint32_t* r, uint32_t saddr) {
    asm volatile("ldmatrix.sync.aligned.m8n8.x4.shared.b16 {%0,%1,%2,%3}, [%4];"
        : "=r"(r[0]), "=r"(r[1]), "=r"(r[2]), "=r"(r[3]) : "r"(saddr));
}
__device__ __forceinline__ void ldm_x4_t(uint32_t* r, uint32_t saddr) {
    asm volatile("ldmatrix.sync.aligned.m8n8.x4.trans.shared.b16 {%0,%1,%2,%3}, [%4];"
        : "=r"(r[0]), "=r"(r[1]), "=r"(r[2]), "=r"(r[3]) : "r"(saddr));
}
__device__ __forceinline__ uint32_t pack2h(float v0, float v1) {
    __half2 t; t.x = __float2half_rn(v0); t.y = __float2half_rn(v1);
    return *reinterpret_cast<uint32_t*>(&t);
}
// global token row for window w (0..255), token q (0..63), batch b
__device__ __forceinline__ int grow1(int b, int w, int q) {
    return ((b * 256 + (w >> 2) * 4 + (q >> 4)) * 64 + (w & 3) * 16 + (q & 15));
}

// ---------------------------------------------------------------- prologue 1:
// A_w = deg_w @ edge_w. One CTA per window; 4x4 register tile per thread,
// k unrolled x4 with float4 loads both sides (smem-bandwidth optimized).
__global__ void __launch_bounds__(256)
pack_A_kernel(const float* __restrict__ edge, const float* __restrict__ deg) {
    __shared__ float eg[64 * 64];   // [k][q]
    __shared__ float dg[64 * 64];   // [p][k]
    const int w = blockIdx.x;
    const int tid = threadIdx.x;
    {
        const float4* eG = (const float4*)(edge + (size_t)w * 4096);
        const float4* dG = (const float4*)(deg + (size_t)w * 4096);
        float4* eS = (float4*)eg;
        float4* dS = (float4*)dg;
        for (int i = tid; i < 1024; i += 256) { eS[i] = eG[i]; dS[i] = dG[i]; }
    }
    __syncthreads();
    const int row0 = (tid >> 4) * 4;      // 0..60
    const int col0 = (tid & 15) * 4;      // 0..60
    float acc[4][4];
#pragma unroll
    for (int r = 0; r < 4; r++)
#pragma unroll
        for (int c = 0; c < 4; c++) acc[r][c] = 0.f;
#pragma unroll 4
    for (int k4 = 0; k4 < 16; k4++) {
        float4 dv[4], ev[4];
#pragma unroll
        for (int r = 0; r < 4; r++) dv[r] = *(const float4*)&dg[(row0 + r) * 64 + k4 * 4];
#pragma unroll
        for (int j = 0; j < 4; j++) ev[j] = *(const float4*)&eg[(k4 * 4 + j) * 64 + col0];
#pragma unroll
        for (int r = 0; r < 4; r++) {
            const float d0 = dv[r].x, d1 = dv[r].y, d2 = dv[r].z, d3 = dv[r].w;
#pragma unroll
            for (int c = 0; c < 4; c++) {
                float* pe0 = &((float*)&ev[0].x)[c];
                acc[r][c] = fmaf(d0, ((const float*)&ev[0])[c],
                            fmaf(d1, ((const float*)&ev[1])[c],
                            fmaf(d2, ((const float*)&ev[2])[c],
                            fmaf(d3, ((const float*)&ev[3])[c], acc[r][c]))));
                (void)pe0;
            }
        }
    }
    // write hi/lo planes + rowsums
    float rsum[4];
#pragma unroll
    for (int r = 0; r < 4; r++) {
        __half* bh = g_A_hi + (size_t)w * 64 * 72 + (row0 + r) * 72 + col0;
        __half* bl = g_A_lo + (size_t)w * 64 * 72 + (row0 + r) * 72 + col0;
        float s = 0.f;
#pragma unroll
        for (int c = 0; c < 4; c++) {
            s += acc[r][c];
            __half h = __float2half_rn(acc[r][c]);
            bh[c] = h;
            bl[c] = __float2half_rn(acc[r][c] - __half2float(h));
        }
        rsum[r] = s;
    }
#pragma unroll
    for (int r = 0; r < 4; r++) {
#pragma unroll
        for (int o = 1; o < 16; o <<= 1)
            rsum[r] += __shfl_xor_sync(0xFFFFFFFFu, rsum[r], o);
    }
    if ((tid & 15) == 0) {
#pragma unroll
        for (int r = 0; r < 4; r++) g_Asum[w * 64 + row0 + r] = rsum[r];
    }
}

// ---------------------------------------------------------------- prologue 2:
__global__ void __launch_bounds__(256)
pack_Wp_kernel(const float* __restrict__ Wp) {
    const int n = blockIdx.x, k = threadIdx.x;
    const float v = Wp[n * 256 + k];
    g_Wp[(k >> 5) * (256 * 40) + n * 40 + (k & 31)] = __float2half_rn(v);
}

// ---------------------------------------------------------------- main kernel
__global__ void __launch_bounds__(256, 2)
window_kernel(const float* __restrict__ x,
              const float* __restrict__ gamma,
              const float* __restrict__ beta,
              const float* __restrict__ bp,
              float* __restrict__ out) {
    extern __shared__ char sm[];
    const int tid  = threadIdx.x;
    const int warp = tid >> 5;
    const int lane = tid & 31;
    const int w    = blockIdx.x;
    const int b    = blockIdx.y;
    const uint32_t smb = smem_u32(sm);

    // ---- prefetch Wp chunks 0,1 under the LN pass + GEMM1 -----------------
    {
        const char* g0 = (const char*)g_Wp;
        for (int i = tid; i < 1280; i += 256) cp16(smb + BUF0 + i * 16, g0 + i * 16);
        CP_COMMIT();
        for (int i = tid; i < 1280; i += 256) cp16(smb + BUF1 + i * 16, g0 + 20480 + i * 16);
        CP_COMMIT();
    }

    // ---- single-pass LayerNorm: stats + normalize in regs, write xn row-major
    {
        const float4 gm0 = *(const float4*)(gamma + lane * 4);
        const float4 gm1 = *(const float4*)(gamma + 128 + lane * 4);
        const float4 bt0 = *(const float4*)(beta + lane * 4);
        const float4 bt1 = *(const float4*)(beta + 128 + lane * 4);
        for (int r = 0; r < 8; r++) {
            const int t = warp * 8 + r;
            const float* xr = x + (size_t)grow1(b, w, t) * 256;
            const float4 v0 = *(const float4*)(xr + lane * 4);
            const float4 v1 = *(const float4*)(xr + 128 + lane * 4);
            float s  = v0.x + v0.y + v0.z + v0.w + v1.x + v1.y + v1.z + v1.w;
            float s2 = v0.x*v0.x + v0.y*v0.y + v0.z*v0.z + v0.w*v0.w
                     + v1.x*v1.x + v1.y*v1.y + v1.z*v1.z + v1.w*v1.w;
#pragma unroll
            for (int o = 16; o > 0; o >>= 1) {
                s  += __shfl_xor_sync(0xFFFFFFFFu, s,  o);
                s2 += __shfl_xor_sync(0xFFFFFFFFu, s2, o);
            }
            const float mean = s * (1.f / 256.f);
            const float rstd = rsqrtf(s2 * (1.f / 256.f) - mean * mean + 1e-5f);
            uint2 u0, u1;
            u0.x = pack2h((v0.x - mean) * rstd * gm0.x + bt0.x,
                          (v0.y - mean) * rstd * gm0.y + bt0.y);
            u0.y = pack2h((v0.z - mean) * rstd * gm0.z + bt0.z,
                          (v0.w - mean) * rstd * gm0.w + bt0.w);
            u1.x = pack2h((v1.x - mean) * rstd * gm1.x + bt1.x,
                          (v1.y - mean) * rstd * gm1.y + bt1.y);
            u1.y = pack2h((v1.z - mean) * rstd * gm1.z + bt1.z,
                          (v1.w - mean) * rstd * gm1.w + bt1.w);
            *(uint2*)(sm + XN_RM + t * T_STRIDE + lane * 8)       = u0;
            *(uint2*)(sm + XN_RM + t * T_STRIDE + 256 + lane * 8) = u1;
        }
    }
    __syncthreads();

    // warp tile: 32 (m) x 64 (n)
    const int wm = (warp & 1) * 32;
    const int wn = (warp >> 1) * 64;
    const int r4 = lane >> 2;          // 0..7
    const int j4 = (lane & 3) * 4;     // byte offset of k-pair
    // ldmatrix lane addressing
    const int lmA = lane & 15;                               // A row within 16 (non-trans)
    const int lkA = (lane >> 4) * 16;                        // A k-byte offset
    const int ktB = (lane & 7) + ((lane >> 3) & 1) * 8;      // trans-B k row
    const int nOB = (lane >> 4) * 8;                         // trans-B n offset

    float D[2][8][4];
#pragma unroll
    for (int mb = 0; mb < 2; mb++)
#pragma unroll
        for (int nb = 0; nb < 8; nb++)
#pragma unroll
            for (int v = 0; v < 4; v++) D[mb][nb][v] = 0.f;

    // ---- GEMM1: t = A_w @ xn  (K=64; A hi/lo from L2, xn via ldmatrix.trans)
    {
        const char* gAh = (const char*)(g_A_hi + (size_t)w * 64 * 72);
        const char* gAl = (const char*)(g_A_lo + (size_t)w * 64 * 72);
#pragma unroll
        for (int ks = 0; ks < 4; ks++) {
            uint32_t Ah[2][4], Al[2][4];
#pragma unroll
            for (int mb = 0; mb < 2; mb++) {
                const int aoff = (wm + mb * 16 + r4) * A_STRIDE + ks * 32 + j4;
                Ah[mb][0] = *(const uint32_t*)(gAh + aoff);
                Ah[mb][1] = *(const uint32_t*)(gAh + aoff + 8 * A_STRIDE);
                Ah[mb][2] = *(const uint32_t*)(gAh + aoff + 16);
                Ah[mb][3] = *(const uint32_t*)(gAh + aoff + 8 * A_STRIDE + 16);
                Al[mb][0] = *(const uint32_t*)(gAl + aoff);
                Al[mb][1] = *(const uint32_t*)(gAl + aoff + 8 * A_STRIDE);
                Al[mb][2] = *(const uint32_t*)(gAl + aoff + 16);
                Al[mb][3] = *(const uint32_t*)(gAl + aoff + 8 * A_STRIDE + 16);
            }
            uint32_t Bv[4][4];
#pragma unroll
            for (int P = 0; P < 4; P++)
                ldm_x4_t(Bv[P], smb + XN_RM + (ks * 16 + ktB) * T_STRIDE + (wn + P * 16 + nOB) * 2);
#pragma unroll
            for (int nb = 0; nb < 8; nb++) {
                const uint32_t b0 = Bv[nb >> 1][(nb & 1) * 2];
                const uint32_t b1 = Bv[nb >> 1][(nb & 1) * 2 + 1];
#pragma unroll
                for (int mb = 0; mb < 2; mb++) {
                    mma16816(D[mb][nb], Ah[mb], b0, b1);
                    mma16816(D[mb][nb], Al[mb], b0, b1);
                }
            }
        }
    }
    __syncthreads();   // all xn reads done; region becomes t_hi

    // ---- store t as single fp16 plane, row-major [m][k] -------------------
#pragma unroll
    for (int mb = 0; mb < 2; mb++) {
#pragma unroll
        for (int nb = 0; nb < 8; nb++) {
            const int m0 = wm + mb * 16 + r4;
            const int n0 = wn + nb * 8 + (lane & 3) * 2;
            float* d = D[mb][nb];
            *(uint32_t*)(sm + T_HI + m0 * T_STRIDE + n0 * 2)       = pack2h(d[0], d[1]);
            *(uint32_t*)(sm + T_HI + (m0 + 8) * T_STRIDE + n0 * 2) = pack2h(d[2], d[3]);
        }
    }

    // zero accumulators for GEMM2
#pragma unroll
    for (int mb = 0; mb < 2; mb++)
#pragma unroll
        for (int nb = 0; nb < 8; nb++)
#pragma unroll
            for (int v = 0; v < 4; v++) D[mb][nb][v] = 0.f;

    // ---- GEMM2: out = t @ Wp^T  (K=256, 8 chunks of 32, double-buffered) --
    for (int ch = 0; ch < 8; ch++) {
        if (ch < 7) { CP_WAIT1(); } else { CP_WAIT0(); }
        __syncthreads();   // orders t stores (ch=0) + buffer reuse + cp arrivals
        const int bufo = (ch & 1) ? BUF1 : BUF0;
#pragma unroll
        for (int ks = 0; ks < 2; ks++) {
            uint32_t Ah[2][4];
#pragma unroll
            for (int mb = 0; mb < 2; mb++) {
                const uint32_t abase = smb + (wm + mb * 16 + lmA) * T_STRIDE + ch * 64 + ks * 32 + lkA;
                ldm_x4(Ah[mb], abase + T_HI);
            }
            uint32_t Bv[4][4];
#pragma unroll
            for (int P = 0; P < 4; P++)
                ldm_x4(Bv[P], smb + bufo + (wn + P * 16 + (lane & 7) + ((lane >> 4) & 1) * 8) * WP_STRIDE
                              + ks * 32 + ((lane >> 3) & 1) * 16);
#pragma unroll
            for (int nb = 0; nb < 8; nb++) {
                const uint32_t b0 = Bv[nb >> 1][(nb & 1) * 2];
                const uint32_t b1 = Bv[nb >> 1][(nb & 1) * 2 + 1];
#pragma unroll
                for (int mb = 0; mb < 2; mb++)
                    mma16816(D[mb][nb], Ah[mb], b0, b1);
            }
        }
        __syncthreads();   // all warps done with this buffer
        if (ch < 6) {      // refill with chunk ch+2
            const uint32_t sb = smb + bufo;
            const char* g = (const char*)g_Wp + (ch + 2) * 20480;
            for (int i = tid; i < 1280; i += 256) cp16(sb + i * 16, g + i * 16);
            CP_COMMIT();
        }
    }

    // ---- epilogue: out = D + rowsum(A)[m]*bp[n], window-reverse -----------
#pragma unroll
    for (int mb = 0; mb < 2; mb++) {
        const int m0 = wm + mb * 16 + r4;
        const int rowA = grow1(b, w, m0);
        const int rowB = grow1(b, w, m0 + 8);
        const float sA = g_Asum[w * 64 + m0];
        const float sB = g_Asum[w * 64 + m0 + 8];
#pragma unroll
        for (int nb = 0; nb < 8; nb++) {
            const int n0 = wn + nb * 8 + (lane & 3) * 2;
            const float2 bpv = *(const float2*)(bp + n0);
            float* d = D[mb][nb];
            float2 z0, z1;
            z0.x = d[0] + sA * bpv.x;  z0.y = d[1] + sA * bpv.y;
            z1.x = d[2] + sB * bpv.x;  z1.y = d[3] + sB * bpv.y;
            *(float2*)(out + (size_t)rowA * 256 + n0) = z0;
            *(float2*)(out + (size_t)rowB * 256 + n0) = z1;
        }
    }
}

// ---------------------------------------------------------------- launch
extern "C" void kernel_launch(void* const* d_in, const int* in_sizes, int n_in,
                              void* d_out, int out_size) {
    (void)in_sizes; (void)n_in; (void)out_size;
    const float* x     = (const float*)d_in[0];
    const float* gamma = (const float*)d_in[1];
    const float* beta  = (const float*)d_in[2];
    const float* Wp    = (const float*)d_in[3];
    const float* bp    = (const float*)d_in[4];
    const float* edge  = (const float*)d_in[5];
    const float* deg   = (const float*)d_in[6];
    float* out = (float*)d_out;

    pack_A_kernel<<<NWIN_, 256>>>(edge, deg);
    pack_Wp_kernel<<<256, 256>>>(Wp);

    cudaFuncSetAttribute(window_kernel, cudaFuncAttributeMaxDynamicSharedMemorySize, SMEM_TOTAL);
    window_kernel<<<dim3(NWIN_, B_), 256, SMEM_TOTAL>>>(x, gamma, beta, bp, out);
}

// round 15
// speedup vs baseline: 1.3770x; 1.0593x over previous
#include <cuda_runtime.h>
#include <cuda_fp16.h>
#include <cstdint>

// ---------------------------------------------------------------- constants
#define B_     8
#define L_     64
#define NWIN_  256

// strides (bytes)
#define A_STRIDE   144   // A row stride (72 fp16)
#define WP_STRIDE  80    // 32 fp16 used (64B) + pad
#define T_STRIDE   528   // 256 fp16 used (512B) + pad

// smem layout (bytes) -- compacted
#define XN_RM   0        // 64 x 528 = 33792 ; reused as t_hi after GEMM1
#define T_HI    0
#define BUF0    33792    // Wp chunk buf0: 256*80 = 20480
#define BUF1    54272    // buf1 -> ends 74752
#define A_HI_SM 74752    // 64*144 = 9216
#define A_LO_SM 83968    // 9216 -> ends 93184
#define SMEM_TOTAL 93184

// ---------------------------------------------------------------- device scratch
__device__ __half g_A_hi[NWIN_ * 64 * 72];   // [w][row][72]
__device__ __half g_A_lo[NWIN_ * 64 * 72];
__device__ __half g_Wp[8 * 256 * 40];        // [chunk k=32][n][40]
__device__ float  g_Asum[NWIN_ * 64];

// ---------------------------------------------------------------- helpers
__device__ __forceinline__ uint32_t smem_u32(const void* p) {
    uint32_t a;
    asm("{ .reg .u64 t; cvta.to.shared.u64 t, %1; cvt.u32.u64 %0, t; }" : "=r"(a) : "l"(p));
    return a;
}
__device__ __forceinline__ void cp16(uint32_t saddr, const void* g) {
    asm volatile("cp.async.cg.shared.global [%0], [%1], 16;" :: "r"(saddr), "l"(g) : "memory");
}
#define CP_COMMIT() asm volatile("cp.async.commit_group;" ::: "memory")
#define CP_WAIT(n)  asm volatile("cp.async.wait_group %0;" :: "n"(n) : "memory")

__device__ __forceinline__ void mma16816(float* d, const uint32_t* a, uint32_t b0, uint32_t b1) {
    asm volatile(
        "mma.sync.aligned.m16n8k16.row.col.f32.f16.f16.f32 "
        "{%0,%1,%2,%3}, {%4,%5,%6,%7}, {%8,%9}, {%0,%1,%2,%3};"
        : "+f"(d[0]), "+f"(d[1]), "+f"(d[2]), "+f"(d[3])
        : "r"(a[0]), "r"(a[1]), "r"(a[2]), "r"(a[3]), "r"(b0), "r"(b1));
}
__device__ __forceinline__ void ldm_x4(uint32_t* r, uint32_t saddr) {
    asm volatile("ldmatrix.sync.aligned.m8n8.x4.shared.b16 {%0,%1,%2,%3}, [%4];"
        : "=r"(r[0]), "=r"(r[1]), "=r"(r[2]), "=r"(r[3]) : "r"(saddr));
}
__device__ __forceinline__ void ldm_x4_t(uint32_t* r, uint32_t saddr) {
    asm volatile("ldmatrix.sync.aligned.m8n8.x4.trans.shared.b16 {%0,%1,%2,%3}, [%4];"
        : "=r"(r[0]), "=r"(r[1]), "=r"(r[2]), "=r"(r[3]) : "r"(saddr));
}
__device__ __forceinline__ uint32_t pack2h(float v0, float v1) {
    __half2 t; t.x = __float2half_rn(v0); t.y = __float2half_rn(v1);
    return *reinterpret_cast<uint32_t*>(&t);
}
// global token row for window w (0..255), token q (0..63), batch b
__device__ __forceinline__ int grow1(int b, int w, int q) {
    return ((b * 256 + (w >> 2) * 4 + (q >> 4)) * 64 + (w & 3) * 16 + (q & 15));
}

// ---------------------------------------------------------------- prologue (merged):
// bid < 512 : half-window of A_w = deg_w @ edge_w (32 rows), 4x4 reg tiles
// bid >= 512: pack_Wp row n = bid-512
__global__ void __launch_bounds__(256)
prologue_kernel(const float* __restrict__ edge, const float* __restrict__ deg,
                const float* __restrict__ Wp) {
    const int tid = threadIdx.x;
    if (blockIdx.x >= 512) {
        const int n = blockIdx.x - 512, k = tid;
        const float v = Wp[n * 256 + k];
        g_Wp[(k >> 5) * (256 * 40) + n * 40 + (k & 31)] = __float2half_rn(v);
        return;
    }
    __shared__ float eg[64 * 64];   // [k][q] full
    __shared__ float dg[32 * 64];   // [p][k] half
    const int w = blockIdx.x >> 1, half = blockIdx.x & 1;
    {
        const float4* eG = (const float4*)(edge + (size_t)w * 4096);
        float4* eS = (float4*)eg;
        for (int i = tid; i < 1024; i += 256) eS[i] = eG[i];
        const float4* dG = (const float4*)(deg + (size_t)w * 4096 + half * 2048);
        float4* dS = (float4*)dg;
        for (int i = tid; i < 512; i += 256) dS[i] = dG[i];
    }
    __syncthreads();
    // 32 rows x 64 cols: 256 threads -> thread tile 4x4 with (tid>>4) in 0..15 mapping 2 row-quads
    const int row0 = (tid >> 4) * 2;      // 0..30, covers 2 rows... need 4 rows: use 8x32 grid
    // regrid: 8 col-groups x 32 row-... simpler: tid>>5 -> rowq (0..7) *4 rows, tid&31 -> col pair *2
    const int rq   = (tid >> 5) * 4;      // row0 0..28 step 4
    const int cq   = (tid & 31) * 2;      // col0 0..62 step 2
    float acc[4][2];
#pragma unroll
    for (int r = 0; r < 4; r++) { acc[r][0] = 0.f; acc[r][1] = 0.f; }
#pragma unroll 4
    for (int k4 = 0; k4 < 16; k4++) {
        float4 dv[4];
        float2 ev[4];
#pragma unroll
        for (int r = 0; r < 4; r++) dv[r] = *(const float4*)&dg[(rq + r) * 64 + k4 * 4];
#pragma unroll
        for (int j = 0; j < 4; j++) ev[j] = *(const float2*)&eg[(k4 * 4 + j) * 64 + cq];
#pragma unroll
        for (int r = 0; r < 4; r++) {
            acc[r][0] = fmaf(dv[r].x, ev[0].x, fmaf(dv[r].y, ev[1].x,
                        fmaf(dv[r].z, ev[2].x, fmaf(dv[r].w, ev[3].x, acc[r][0]))));
            acc[r][1] = fmaf(dv[r].x, ev[0].y, fmaf(dv[r].y, ev[1].y,
                        fmaf(dv[r].z, ev[2].y, fmaf(dv[r].w, ev[3].y, acc[r][1]))));
        }
    }
    float rsum[4];
#pragma unroll
    for (int r = 0; r < 4; r++) {
        const int p = half * 32 + rq + r;
        __half* bh = g_A_hi + (size_t)w * 64 * 72 + p * 72 + cq;
        __half* bl = g_A_lo + (size_t)w * 64 * 72 + p * 72 + cq;
        float s = 0.f;
#pragma unroll
        for (int c = 0; c < 2; c++) {
            s += acc[r][c];
            __half h = __float2half_rn(acc[r][c]);
            bh[c] = h;
            bl[c] = __float2half_rn(acc[r][c] - __half2float(h));
        }
        rsum[r] = s;
    }
#pragma unroll
    for (int r = 0; r < 4; r++) {
#pragma unroll
        for (int o = 1; o < 32; o <<= 1)
            rsum[r] += __shfl_xor_sync(0xFFFFFFFFu, rsum[r], o);
    }
    if ((tid & 31) == 0) {
#pragma unroll
        for (int r = 0; r < 4; r++) g_Asum[w * 64 + half * 32 + rq + r] = rsum[r];
    }
}

// ---------------------------------------------------------------- main kernel
__global__ void __launch_bounds__(256, 2)
window_kernel(const float* __restrict__ x,
              const float* __restrict__ gamma,
              const float* __restrict__ beta,
              const float* __restrict__ bp,
              float* __restrict__ out) {
    extern __shared__ char sm[];
    const int tid  = threadIdx.x;
    const int warp = tid >> 5;
    const int lane = tid & 31;
    const int w    = blockIdx.x;
    const int b    = blockIdx.y;
    const uint32_t smb = smem_u32(sm);

    // ---- group 0: stage A hi/lo (18432 B); groups 1,2: Wp chunks 0,1 ------
    {
        const char* gAh = (const char*)(g_A_hi + (size_t)w * 64 * 72);
        const char* gAl = (const char*)(g_A_lo + (size_t)w * 64 * 72);
        for (int i = tid; i < 576; i += 256) {
            cp16(smb + A_HI_SM + i * 16, gAh + i * 16);
            cp16(smb + A_LO_SM + i * 16, gAl + i * 16);
        }
        CP_COMMIT();
        const char* g0 = (const char*)g_Wp;
        for (int i = tid; i < 1280; i += 256) cp16(smb + BUF0 + i * 16, g0 + i * 16);
        CP_COMMIT();
        for (int i = tid; i < 1280; i += 256) cp16(smb + BUF1 + i * 16, g0 + 20480 + i * 16);
        CP_COMMIT();
    }

    // ---- single-pass LayerNorm: stats + normalize in regs, write xn row-major
    {
        const float4 gm0 = *(const float4*)(gamma + lane * 4);
        const float4 gm1 = *(const float4*)(gamma + 128 + lane * 4);
        const float4 bt0 = *(const float4*)(beta + lane * 4);
        const float4 bt1 = *(const float4*)(beta + 128 + lane * 4);
        for (int r = 0; r < 8; r++) {
            const int t = warp * 8 + r;
            const float* xr = x + (size_t)grow1(b, w, t) * 256;
            const float4 v0 = *(const float4*)(xr + lane * 4);
            const float4 v1 = *(const float4*)(xr + 128 + lane * 4);
            float s  = v0.x + v0.y + v0.z + v0.w + v1.x + v1.y + v1.z + v1.w;
            float s2 = v0.x*v0.x + v0.y*v0.y + v0.z*v0.z + v0.w*v0.w
                     + v1.x*v1.x + v1.y*v1.y + v1.z*v1.z + v1.w*v1.w;
#pragma unroll
            for (int o = 16; o > 0; o >>= 1) {
                s  += __shfl_xor_sync(0xFFFFFFFFu, s,  o);
                s2 += __shfl_xor_sync(0xFFFFFFFFu, s2, o);
            }
            const float mean = s * (1.f / 256.f);
            const float rstd = rsqrtf(s2 * (1.f / 256.f) - mean * mean + 1e-5f);
            uint2 u0, u1;
            u0.x = pack2h((v0.x - mean) * rstd * gm0.x + bt0.x,
                          (v0.y - mean) * rstd * gm0.y + bt0.y);
            u0.y = pack2h((v0.z - mean) * rstd * gm0.z + bt0.z,
                          (v0.w - mean) * rstd * gm0.w + bt0.w);
            u1.x = pack2h((v1.x - mean) * rstd * gm1.x + bt1.x,
                          (v1.y - mean) * rstd * gm1.y + bt1.y);
            u1.y = pack2h((v1.z - mean) * rstd * gm1.z + bt1.z,
                          (v1.w - mean) * rstd * gm1.w + bt1.w);
            *(uint2*)(sm + XN_RM + t * T_STRIDE + lane * 8)       = u0;
            *(uint2*)(sm + XN_RM + t * T_STRIDE + 256 + lane * 8) = u1;
        }
    }
    CP_WAIT(2);          // A staged (Wp chunks may still be in flight)
    __syncthreads();

    // warp tile: 32 (m) x 64 (n)
    const int wm = (warp & 1) * 32;
    const int wn = (warp >> 1) * 64;
    const int r4 = lane >> 2;          // 0..7
    // ldmatrix lane addressing
    const int lmA = lane & 15;                               // A row within 16 (non-trans)
    const int lkA = (lane >> 4) * 16;                        // A k-byte offset
    const int ktB = (lane & 7) + ((lane >> 3) & 1) * 8;      // trans-B k row
    const int nOB = (lane >> 4) * 8;                         // trans-B n offset

    float D[2][8][4];
#pragma unroll
    for (int mb = 0; mb < 2; mb++)
#pragma unroll
        for (int nb = 0; nb < 8; nb++)
#pragma unroll
            for (int v = 0; v < 4; v++) D[mb][nb][v] = 0.f;

    // ---- GEMM1: t = A_w @ xn  (K=64; A hi/lo via ldmatrix from smem) ------
    {
#pragma unroll
        for (int ks = 0; ks < 4; ks++) {
            uint32_t Ah[2][4], Al[2][4];
#pragma unroll
            for (int mb = 0; mb < 2; mb++) {
                const uint32_t abase = smb + (wm + mb * 16 + lmA) * A_STRIDE + ks * 32 + lkA;
                ldm_x4(Ah[mb], abase + A_HI_SM);
                ldm_x4(Al[mb], abase + A_LO_SM);
            }
            uint32_t Bv[4][4];
#pragma unroll
            for (int P = 0; P < 4; P++)
                ldm_x4_t(Bv[P], smb + XN_RM + (ks * 16 + ktB) * T_STRIDE + (wn + P * 16 + nOB) * 2);
#pragma unroll
            for (int nb = 0; nb < 8; nb++) {
                const uint32_t b0 = Bv[nb >> 1][(nb & 1) * 2];
                const uint32_t b1 = Bv[nb >> 1][(nb & 1) * 2 + 1];
#pragma unroll
                for (int mb = 0; mb < 2; mb++) {
                    mma16816(D[mb][nb], Ah[mb], b0, b1);
                    mma16816(D[mb][nb], Al[mb], b0, b1);
                }
            }
        }
    }
    __syncthreads();   // all xn reads done; region becomes t_hi

    // ---- store t as single fp16 plane, row-major [m][k] -------------------
#pragma unroll
    for (int mb = 0; mb < 2; mb++) {
#pragma unroll
        for (int nb = 0; nb < 8; nb++) {
            const int m0 = wm + mb * 16 + r4;
            const int n0 = wn + nb * 8 + (lane & 3) * 2;
            float* d = D[mb][nb];
            *(uint32_t*)(sm + T_HI + m0 * T_STRIDE + n0 * 2)       = pack2h(d[0], d[1]);
            *(uint32_t*)(sm + T_HI + (m0 + 8) * T_STRIDE + n0 * 2) = pack2h(d[2], d[3]);
        }
    }

    // zero accumulators for GEMM2
#pragma unroll
    for (int mb = 0; mb < 2; mb++)
#pragma unroll
        for (int nb = 0; nb < 8; nb++)
#pragma unroll
            for (int v = 0; v < 4; v++) D[mb][nb][v] = 0.f;

    // ---- GEMM2: out = t @ Wp^T  (K=256, 8 chunks of 32, double-buffered) --
    for (int ch = 0; ch < 8; ch++) {
        if (ch < 7) { CP_WAIT(1); } else { CP_WAIT(0); }
        __syncthreads();   // orders t stores (ch=0) + buffer reuse + cp arrivals
        const int bufo = (ch & 1) ? BUF1 : BUF0;
#pragma unroll
        for (int ks = 0; ks < 2; ks++) {
            uint32_t Ah[2][4];
#pragma unroll
            for (int mb = 0; mb < 2; mb++) {
                const uint32_t abase = smb + (wm + mb * 16 + lmA) * T_STRIDE + ch * 64 + ks * 32 + lkA;
                ldm_x4(Ah[mb], abase + T_HI);
            }
            uint32_t Bv[4][4];
#pragma unroll
            for (int P = 0; P < 4; P++)
                ldm_x4(Bv[P], smb + bufo + (wn + P * 16 + (lane & 7) + ((lane >> 4) & 1) * 8) * WP_STRIDE
                              + ks * 32 + ((lane >> 3) & 1) * 16);
#pragma unroll
            for (int nb = 0; nb < 8; nb++) {
                const uint32_t b0 = Bv[nb >> 1][(nb & 1) * 2];
                const uint32_t b1 = Bv[nb >> 1][(nb & 1) * 2 + 1];
#pragma unroll
                for (int mb = 0; mb < 2; mb++)
                    mma16816(D[mb][nb], Ah[mb], b0, b1);
            }
        }
        __syncthreads();   // all warps done with this buffer
        if (ch < 6) {      // refill with chunk ch+2
            const uint32_t sb = smb + bufo;
            const char* g = (const char*)g_Wp + (ch + 2) * 20480;
            for (int i = tid; i < 1280; i += 256) cp16(sb + i * 16, g + i * 16);
            CP_COMMIT();
        }
    }

    // ---- epilogue: out = D + rowsum(A)[m]*bp[n], window-reverse -----------
#pragma unroll
    for (int mb = 0; mb < 2; mb++) {
        const int m0 = wm + mb * 16 + r4;
        const int rowA = grow1(b, w, m0);
        const int rowB = grow1(b, w, m0 + 8);
        const float sA = g_Asum[w * 64 + m0];
        const float sB = g_Asum[w * 64 + m0 + 8];
#pragma unroll
        for (int nb = 0; nb < 8; nb++) {
            const int n0 = wn + nb * 8 + (lane & 3) * 2;
            const float2 bpv = *(const float2*)(bp + n0);
            float* d = D[mb][nb];
            float2 z0, z1;
            z0.x = d[0] + sA * bpv.x;  z0.y = d[1] + sA * bpv.y;
            z1.x = d[2] + sB * bpv.x;  z1.y = d[3] + sB * bpv.y;
            *(float2*)(out + (size_t)rowA * 256 + n0) = z0;
            *(float2*)(out + (size_t)rowB * 256 + n0) = z1;
        }
    }
}

// ---------------------------------------------------------------- launch
extern "C" void kernel_launch(void* const* d_in, const int* in_sizes, int n_in,
                              void* d_out, int out_size) {
    (void)in_sizes; (void)n_in; (void)out_size;
    const float* x     = (const float*)d_in[0];
    const float* gamma = (const float*)d_in[1];
    const float* beta  = (const float*)d_in[2];
    const float* Wp    = (const float*)d_in[3];
    const float* bp    = (const float*)d_in[4];
    const float* edge  = (const float*)d_in[5];
    const float* deg   = (const float*)d_in[6];
    float* out = (float*)d_out;

    prologue_kernel<<<512 + 256, 256>>>(edge, deg, Wp);

    cudaFuncSetAttribute(window_kernel, cudaFuncAttributeMaxDynamicSharedMemorySize, SMEM_TOTAL);
    window_kernel<<<dim3(NWIN_, B_), 256, SMEM_TOTAL>>>(x, gamma, beta, bp, out);
}